// round 1
// baseline (speedup 1.0000x reference)
#include <cuda_runtime.h>
#include <math.h>

#define NA 48            // atoms per molecule (fixed by problem)
#define NS 4             // species
#define NSHFR 16
#define NSHFA 4
#define NSHFZ 8
#define RAD_FEAT (NS * NSHFR)              // 64
#define ANG_SUB (NSHFA * NSHFZ)            // 32
#define NPAIRS_SP (NS * (NS + 1) / 2)      // 10
#define AEV_LEN (RAD_FEAT + NPAIRS_SP * ANG_SUB)  // 384
#define RCR_F 5.2f
#define RCA_F 3.5f
#define PI_F 3.14159265358979323846f

__device__ __forceinline__ int triu_idx(int a, int b) {
    int lo = min(a, b), hi = max(a, b);
    // index into upper-triangular enumeration of (NS x NS)
    return lo * NS - (lo * (lo - 1)) / 2 + (hi - lo);
}

__global__ __launch_bounds__(128, 8)
void aev_kernel(const float* __restrict__ coords,   // (M, A, 3)
                const float* __restrict__ gEtaR,    // (1,)
                const float* __restrict__ gShfR,    // (16,)
                const float* __restrict__ gEtaA,    // (1,)
                const float* __restrict__ gZeta,    // (1,)
                const float* __restrict__ gShfA,    // (4,)
                const float* __restrict__ gShfZ,    // (8,)
                const int*   __restrict__ species,  // (M, A)
                float* __restrict__ out)            // (M, A, 384)
{
    const int i = blockIdx.x;   // atom index within molecule
    const int m = blockIdx.y;   // molecule index
    const int tid = threadIdx.x;
    const int nthr = blockDim.x;

    __shared__ float sx[NA], sy[NA], sz[NA];
    __shared__ int   ssp[NA];
    __shared__ float shfr[NSHFR], shfa[NSHFA], shfz[NSHFZ];
    __shared__ float s_etaR, s_etaA, s_zeta;
    __shared__ float aev[AEV_LEN];
    // compacted neighbor list (within RCA) for the angular part
    __shared__ float nvx[NA], nvy[NA], nvz[NA], nd[NA], nfc[NA];
    __shared__ int   nsp[NA];
    __shared__ int   ncount;

    // ---- load molecule data + params into SMEM, zero accumulators ----
    if (tid < NA) {
        const float* c = coords + ((size_t)m * NA + tid) * 3;
        sx[tid] = c[0];
        sy[tid] = c[1];
        sz[tid] = c[2];
        ssp[tid] = species[(size_t)m * NA + tid];
    }
    if (tid < NSHFR) shfr[tid] = gShfR[tid];
    if (tid < NSHFA) shfa[tid] = gShfA[tid];
    if (tid < NSHFZ) shfz[tid] = gShfZ[tid];
    if (tid == 0) {
        s_etaR = gEtaR[0];
        s_etaA = gEtaA[0];
        s_zeta = gZeta[0];
        ncount = 0;
    }
    for (int c = tid; c < AEV_LEN; c += nthr) aev[c] = 0.0f;
    __syncthreads();

    const float cx = sx[i], cy = sy[i], cz = sz[i];
    const float etaR = s_etaR, etaA = s_etaA, zeta = s_zeta;

    // ---- radial part + neighbor compaction ----
    for (int j = tid; j < NA; j += nthr) {
        if (j == i) continue;
        float dx = sx[j] - cx;
        float dy = sy[j] - cy;
        float dz = sz[j] - cz;
        float d = sqrtf(dx * dx + dy * dy + dz * dz);
        if (d <= RCR_F) {
            float fc = 0.5f * cosf(d * (PI_F / RCR_F)) + 0.5f;
            int base = ssp[j] * NSHFR;
            #pragma unroll
            for (int k = 0; k < NSHFR; k++) {
                float t = d - shfr[k];
                float v = 0.25f * expf(-etaR * t * t) * fc;
                atomicAdd(&aev[base + k], v);
            }
        }
        if (d <= RCA_F) {
            int slot = atomicAdd(&ncount, 1);
            nvx[slot] = dx;
            nvy[slot] = dy;
            nvz[slot] = dz;
            nd[slot]  = d;
            nfc[slot] = 0.5f * cosf(d * (PI_F / RCA_F)) + 0.5f;
            nsp[slot] = ssp[j];
        }
    }
    __syncthreads();

    // ---- angular part: all unordered pairs of in-cutoff neighbors ----
    const int n = ncount;
    const int npairs = n * (n - 1) / 2;
    for (int p = tid; p < npairs; p += nthr) {
        // map linear p -> (a, b) with a < b
        int a = 0, rem = p;
        while (rem >= n - 1 - a) { rem -= n - 1 - a; a++; }
        int b = a + 1 + rem;

        float d1 = nd[a], d2 = nd[b];
        float dot = nvx[a] * nvx[b] + nvy[a] * nvy[b] + nvz[a] * nvz[b];
        float cosv = 0.95f * dot / (fmaxf(d1, 1e-8f) * fmaxf(d2, 1e-8f));
        float ang = acosf(cosv);
        float dm = 0.5f * (d1 + d2);
        float fcj2 = 2.0f * nfc[a] * nfc[b];
        int base = RAD_FEAT + triu_idx(nsp[a], nsp[b]) * ANG_SUB;

        float f1[NSHFZ];
        #pragma unroll
        for (int t = 0; t < NSHFZ; t++) {
            float bse = 0.5f * (1.0f + cosf(ang - shfz[t]));
            f1[t] = powf(bse, zeta) * fcj2;
        }
        #pragma unroll
        for (int s = 0; s < NSHFA; s++) {
            float dd = dm - shfa[s];
            float f2 = expf(-etaA * dd * dd);
            #pragma unroll
            for (int t = 0; t < NSHFZ; t++) {
                atomicAdd(&aev[base + s * NSHFZ + t], f1[t] * f2);
            }
        }
    }
    __syncthreads();

    // ---- write out ----
    float* o = out + ((size_t)m * NA + i) * AEV_LEN;
    for (int c = tid; c < AEV_LEN; c += nthr) o[c] = aev[c];
}

extern "C" void kernel_launch(void* const* d_in, const int* in_sizes, int n_in,
                              void* d_out, int out_size) {
    const float* coords = (const float*)d_in[0];
    const float* EtaR   = (const float*)d_in[1];
    const float* ShfR   = (const float*)d_in[2];
    const float* EtaA   = (const float*)d_in[3];
    const float* Zeta   = (const float*)d_in[4];
    const float* ShfA   = (const float*)d_in[5];
    const float* ShfZ   = (const float*)d_in[6];
    const int*   spec   = (const int*)d_in[7];
    float* out = (float*)d_out;

    int MA = in_sizes[7];        // M * A
    int M = MA / NA;

    dim3 grid(NA, M);
    aev_kernel<<<grid, 128>>>(coords, EtaR, ShfR, EtaA, Zeta, ShfA, ShfZ, spec, out);
}